// round 10
// baseline (speedup 1.0000x reference)
#include <cuda_runtime.h>
#include <cuda_bf16.h>
#include <cstdint>

typedef unsigned int u32;

// ============================================================================
// CustomLinear fused q/k/v — mma.sync bf16 hi/lo + smem-staged streaming stores
//   prep_w / prep_x: W and X split to bf16 hi/lo, k-interleaved (R8 layout).
//   main: grid (tokens/8, 3 regions). CTA builds the full 8-token x 1040-float
//   output image for its region in smem (zeros + mma payload + scalars), then
//   streams it to gmem as dense float4s.
// ============================================================================

#define REGION 34078720L           // 8*4096*1040 floats per q/k/v region
#define NTOK   32768

__device__ __align__(16) __nv_bfloat16 g_Wh[8 * 8192];
__device__ __align__(16) __nv_bfloat16 g_Wl[8 * 8192];
__device__ __align__(16) __nv_bfloat16 g_X[4][NTOK * 64];   // 0 x1h 1 x1l 2 x2h 3 x2l
__device__ __align__(16) float2 g_S[NTOK];                  // {s_mid, s_last}

__device__ __forceinline__ int kpos(int kk) {               // kk in 0..15
    return (((kk & 7) >> 1) << 2) + ((kk >> 3) << 1) + (kk & 1);
}

__device__ __forceinline__ void mma_bf16(float* c,
                                         u32 a0, u32 a1, u32 a2, u32 a3,
                                         u32 b0, u32 b1) {
    asm volatile(
        "mma.sync.aligned.m16n8k16.row.col.f32.bf16.bf16.f32 "
        "{%0,%1,%2,%3}, {%4,%5,%6,%7}, {%8,%9}, {%0,%1,%2,%3};"
        : "+f"(c[0]), "+f"(c[1]), "+f"(c[2]), "+f"(c[3])
        : "r"(a0), "r"(a1), "r"(a2), "r"(a3), "r"(b0), "r"(b1));
}

// ---- prep W: 32 blocks, each a quarter of one packed GEMM ----
__global__ void prep_w(const float* __restrict__ Mq, const float* __restrict__ Mk,
                       const float* __restrict__ Mv) {
    int g = blockIdx.x >> 2, quarter = blockIdx.x & 3;
    int r = (g < 2) ? 0 : (g < 4) ? 1 : 2;
    int p = (g < 2) ? g : (g < 4) ? g - 2 : g - 4;
    const float* Mbase = (r == 0) ? Mq : (r == 1) ? Mk : Mv;
    for (int i = threadIdx.x; i < 2048; i += blockDim.x) {
        int idx = quarter * 2048 + i;
        int f = idx >> 6, k = idx & 63;
        int head = 2 * p + (f >> 6);
        float v = __ldg(&Mbase[head * 4096 + (f & 63) * 64 + k]);
        __nv_bfloat16 h = __float2bfloat16(v);
        __nv_bfloat16 l = __float2bfloat16(v - __bfloat162float(h));
        int st = g * 8192 + f * 64 + (k >> 4) * 16 + kpos(k & 15);
        g_Wh[st] = h;
        g_Wl[st] = l;
    }
}

// ---- prep X: x1/x2 hi/lo interleaved + scalar pairs ----
__global__ void prep_x(const float* __restrict__ x) {
    const int total = NTOK * 64;
    for (int idx = blockIdx.x * blockDim.x + threadIdx.x; idx < total;
         idx += gridDim.x * blockDim.x) {
        int t = idx >> 6, k = idx & 63;
        int st = t * 64 + (k >> 4) * 16 + kpos(k & 15);
        float v1 = __ldg(&x[t * 130 + k]);
        float v2 = __ldg(&x[t * 130 + 65 + k]);
        __nv_bfloat16 h1 = __float2bfloat16(v1);
        __nv_bfloat16 h2 = __float2bfloat16(v2);
        g_X[0][st] = h1;
        g_X[1][st] = __float2bfloat16(v1 - __bfloat162float(h1));
        g_X[2][st] = h2;
        g_X[3][st] = __float2bfloat16(v2 - __bfloat162float(h2));
        if (k == 0)
            g_S[t] = make_float2(__ldg(&x[t * 130 + 64]), __ldg(&x[t * 130 + 129]));
    }
}

// ---- per-warp GEMM tile: FR m16-tiles x 8 tokens, scatter into smem image ----
template <int FR>
__device__ __forceinline__ void gemm_tile(
    float* img, const uint2* Ah, const uint2* Al,
    const uint2* Bh, const uint2* Bl, int f0, int g_, int t4)
{
    float c[FR][4];
    #pragma unroll
    for (int fr = 0; fr < FR; fr++)
        { c[fr][0] = 0.f; c[fr][1] = 0.f; c[fr][2] = 0.f; c[fr][3] = 0.f; }

    #pragma unroll
    for (int fr = 0; fr < FR; fr++) {
        #pragma unroll
        for (int kt = 0; kt < 4; kt++) {
            uint2 aH0 = __ldg(Ah + fr * 256 + kt * 4);
            uint2 aH1 = __ldg(Ah + fr * 256 + 128 + kt * 4);
            uint2 aL0 = __ldg(Al + fr * 256 + kt * 4);
            uint2 aL1 = __ldg(Al + fr * 256 + 128 + kt * 4);
            uint2 bH  = __ldcg(Bh + kt * 4);     // CSE'd across fr by compiler
            uint2 bL  = __ldcg(Bl + kt * 4);
            mma_bf16(c[fr], aH0.x, aH1.x, aH0.y, aH1.y, bH.x, bH.y);
            mma_bf16(c[fr], aH0.x, aH1.x, aH0.y, aH1.y, bL.x, bL.y);
            mma_bf16(c[fr], aL0.x, aL1.x, aL0.y, aL1.y, bH.x, bH.y);
        }
    }

    // scatter: c0 (fh, t0), c1 (fh, t0+1), c2 (fh+8, t0), c3 (fh+8, t0+1)
    const int t0 = 2 * t4;
    #pragma unroll
    for (int fr = 0; fr < FR; fr++) {
        const int f = f0 + fr * 16;
        const int sbase = (f >> 6) * 130 + 65 + (f & 63) + g_;
        float* q0 = img + t0 * 1040 + sbase;
        q0[0]    = c[fr][0];
        q0[1040] = c[fr][1];
        q0[8]    = c[fr][2];
        q0[1048] = c[fr][3];
    }
}

// ---- main: CTA = 8 tokens x full region row (1040 floats/token) ----
__global__ void __launch_bounds__(256, 4) qkv_main(
    const float* __restrict__ Bq, const float* __restrict__ Bk,
    float* __restrict__ out)
{
    __shared__ __align__(16) float img[8 * 1040];

    const int tid  = threadIdx.x;
    const int wid  = tid >> 5;
    const int lane = tid & 31;
    const int g_   = lane >> 2;
    const int t4   = lane & 3;
    const int  r   = blockIdx.y;
    const long tok0 = (long)blockIdx.x * 8;

    // zero-fill output image
    float4* im4 = (float4*)img;
    const float4 z4 = make_float4(0.f, 0.f, 0.f, 0.f);
    #pragma unroll
    for (int i = 0; i < 8; i++) im4[tid + i * 256] = z4;
    if (tid < 32) im4[2048 + tid] = z4;          // 2080 total
    __syncthreads();

    // B fragment pointers (token row = g_)
    const __nv_bfloat16* xh = (r == 0) ? g_X[2] : g_X[0];
    const __nv_bfloat16* xl = (r == 0) ? g_X[3] : g_X[1];
    const uint2* Bh = (const uint2*)xh + (tok0 + g_) * 16 + t4;
    const uint2* Bl = (const uint2*)xl + (tok0 + g_) * 16 + t4;

    if (r < 2) {
        // M=256: warp = 32 feats (heads 0..3 matvec)
        const int f0   = wid * 32;
        const int gA   = (r ? 2 : 0) + (wid >> 2);
        const int rowG = (wid & 3) * 32;
        const uint2* Ah = (const uint2*)g_Wh + gA * 2048 + (rowG + g_) * 16 + t4;
        const uint2* Al = (const uint2*)g_Wl + gA * 2048 + (rowG + g_) * 16 + t4;
        gemm_tile<2>(img, Ah, Al, Bh, Bl, f0, g_, t4);

        // scalar slots: heads 0..3 slot 129, heads 4..7 slot 65
        if (tid < 64) {
            int tt = tid >> 3, h = tid & 7;
            const float* Bv = r ? Bk : Bq;
            float b = __ldg(Bv + h);
            float2 s = g_S[tok0 + tt];
            if (h < 4) img[tt * 1040 + h * 130 + 129] = s.y * b;
            else       img[tt * 1040 + h * 130 + 65]  = ((r == 0) ? s.y : s.x) * b;
        }
    } else {
        // M=512: warp = 64 feats = exactly head wid
        const int f0   = wid * 64;
        const int gA   = 4 + (wid >> 1);
        const int rowG = (wid & 1) * 64;
        const uint2* Ah = (const uint2*)g_Wh + gA * 2048 + (rowG + g_) * 16 + t4;
        const uint2* Al = (const uint2*)g_Wl + gA * 2048 + (rowG + g_) * 16 + t4;
        gemm_tile<4>(img, Ah, Al, Bh, Bl, f0, g_, t4);
    }
    __syncthreads();

    // stream image to gmem: 2080 dense float4s
    float4* o4 = (float4*)(out + (long)r * REGION + tok0 * 1040);
    #pragma unroll
    for (int i = 0; i < 8; i++) o4[tid + i * 256] = im4[tid + i * 256];
    if (tid < 32) o4[2048 + tid] = im4[2048 + tid];
}

extern "C" void kernel_launch(void* const* d_in, const int* in_sizes, int n_in,
                              void* d_out, int out_size) {
    const float* x  = (const float*)d_in[0];
    const float* Mq = (const float*)d_in[1];
    const float* Bq = (const float*)d_in[2];
    const float* Mk = (const float*)d_in[3];
    const float* Bk = (const float*)d_in[4];
    const float* Mv = (const float*)d_in[5];
    float* out = (float*)d_out;

    const int tokens = in_sizes[0] / 130;   // 32768
    prep_w<<<32, 256>>>(Mq, Mk, Mv);
    prep_x<<<256, 256>>>(x);
    dim3 grid(tokens / 8, 3);
    qkv_main<<<grid, 256>>>(Bq, Bk, out);
}

// round 11
// speedup vs baseline: 1.4788x; 1.4788x over previous
#include <cuda_runtime.h>
#include <cuda_bf16.h>
#include <cstdint>

typedef unsigned int u32;

// ============================================================================
// CustomLinear fused q/k/v — mma.sync bf16 hi/lo split, global-direct fragments
//   prep: W and X split to bf16 hi/lo, k-interleaved, + per-token scalars.
//   main: grid (8 GEMMs, tokens/64) — GEMM index fastest so the 8 CTAs sharing
//   an X tile are co-scheduled (L2-hot). Warp = 16 feats x 64 tokens.
//   k-interleave within 16-k chunk: [0,1,8,9, 2,3,10,11, 4,5,12,13, 6,7,14,15]
// ============================================================================

#define REGION 34078720L           // 8*4096*1040 floats per q/k/v region
#define NTOK   32768

__device__ __align__(16) __nv_bfloat16 g_Wh[8 * 8192];
__device__ __align__(16) __nv_bfloat16 g_Wl[8 * 8192];
__device__ __align__(16) __nv_bfloat16 g_X[4][NTOK * 64];   // 0 x1h 1 x1l 2 x2h 3 x2l
__device__ __align__(16) float2 g_S[NTOK];                  // {s_mid, s_last}

__device__ __forceinline__ int kpos(int kk) {               // kk in 0..15
    return (((kk & 7) >> 1) << 2) + ((kk >> 3) << 1) + (kk & 1);
}

__device__ __forceinline__ void mma_bf16(float* c,
                                         u32 a0, u32 a1, u32 a2, u32 a3,
                                         u32 b0, u32 b1) {
    asm volatile(
        "mma.sync.aligned.m16n8k16.row.col.f32.bf16.bf16.f32 "
        "{%0,%1,%2,%3}, {%4,%5,%6,%7}, {%8,%9}, {%0,%1,%2,%3};"
        : "+f"(c[0]), "+f"(c[1]), "+f"(c[2]), "+f"(c[3])
        : "r"(a0), "r"(a1), "r"(a2), "r"(a3), "r"(b0), "r"(b1));
}

// ---- merged prep: blocks 0..31 = W quarters, blocks 32..287 = X strided ----
__global__ void prep_all(const float* __restrict__ x,
                         const float* __restrict__ Mq, const float* __restrict__ Mk,
                         const float* __restrict__ Mv) {
    if (blockIdx.x < 32) {
        int g = blockIdx.x >> 2, quarter = blockIdx.x & 3;
        int r = (g < 2) ? 0 : (g < 4) ? 1 : 2;
        int p = (g < 2) ? g : (g < 4) ? g - 2 : g - 4;
        const float* Mbase = (r == 0) ? Mq : (r == 1) ? Mk : Mv;
        for (int i = threadIdx.x; i < 2048; i += blockDim.x) {
            int idx = quarter * 2048 + i;
            int f = idx >> 6, k = idx & 63;
            int head = 2 * p + (f >> 6);
            float v = __ldg(&Mbase[head * 4096 + (f & 63) * 64 + k]);
            __nv_bfloat16 h = __float2bfloat16(v);
            __nv_bfloat16 l = __float2bfloat16(v - __bfloat162float(h));
            int st = g * 8192 + f * 64 + (k >> 4) * 16 + kpos(k & 15);
            g_Wh[st] = h;
            g_Wl[st] = l;
        }
    } else {
        const int total = NTOK * 64;
        for (int idx = (blockIdx.x - 32) * blockDim.x + threadIdx.x; idx < total;
             idx += 256 * blockDim.x) {
            int t = idx >> 6, k = idx & 63;
            int st = t * 64 + (k >> 4) * 16 + kpos(k & 15);
            float v1 = __ldg(&x[t * 130 + k]);
            float v2 = __ldg(&x[t * 130 + 65 + k]);
            __nv_bfloat16 h1 = __float2bfloat16(v1);
            __nv_bfloat16 h2 = __float2bfloat16(v2);
            g_X[0][st] = h1;
            g_X[1][st] = __float2bfloat16(v1 - __bfloat162float(h1));
            g_X[2][st] = h2;
            g_X[3][st] = __float2bfloat16(v2 - __bfloat162float(h2));
            if (k == 0)
                g_S[t] = make_float2(__ldg(&x[t * 130 + 64]), __ldg(&x[t * 130 + 129]));
        }
    }
}

// ---- main: warp = 16 feats x 64 tokens, all operands via LDG.64 ----
__global__ void __launch_bounds__(256, 3) qkv_mma_kernel(
    const float* __restrict__ Bq, const float* __restrict__ Bk,
    float* __restrict__ out)
{
    const int tid  = threadIdx.x;
    const int wid  = tid >> 5;
    const int lane = tid & 31;
    const int g_   = lane >> 2;          // fragment group (A row / B token / C row)
    const int t4   = lane & 3;           // fragment thread  (k pair / C col)

    const int g = blockIdx.x;                       // packed GEMM id (fastest)
    const long tok0 = (long)blockIdx.y * 64;        // token tile
    const int r = (g < 2) ? 0 : (g < 4) ? 1 : 2;    // q / k / v
    const int p = (g < 2) ? g : (g < 4) ? g - 2 : g - 4;
    const int fb = wid * 16;

    // A pointers: uint2 index = row*16 + kt*4 + t4  (row stride 64 bf16 = 16 uint2)
    const uint2* Ah = (const uint2*)g_Wh + g * 2048 + (fb + g_) * 16 + t4;
    const uint2* Al = (const uint2*)g_Wl + g * 2048 + (fb + g_) * 16 + t4;
    // B pointers: token row = tok0 + nt*8 + g_
    const __nv_bfloat16* xh = (r == 0) ? g_X[2] : g_X[0];
    const __nv_bfloat16* xl = (r == 0) ? g_X[3] : g_X[1];
    const uint2* Bh = (const uint2*)xh + (tok0 + g_) * 16 + t4;
    const uint2* Bl = (const uint2*)xl + (tok0 + g_) * 16 + t4;

    float c[8][4];
    #pragma unroll
    for (int nt = 0; nt < 8; nt++)
        { c[nt][0] = 0.f; c[nt][1] = 0.f; c[nt][2] = 0.f; c[nt][3] = 0.f; }

    #pragma unroll
    for (int kt = 0; kt < 4; kt++) {
        // A fragments: {a0,a2} from row fb+g_, {a1,a3} from row fb+8+g_
        uint2 aH0 = __ldg(Ah + kt * 4);
        uint2 aH1 = __ldg(Ah + 128 + kt * 4);
        uint2 aL0 = __ldg(Al + kt * 4);
        uint2 aL1 = __ldg(Al + 128 + kt * 4);

        #pragma unroll
        for (int nh = 0; nh < 2; nh++) {
            // batched B loads: 8 independent LDG.64 in flight before the MMAs
            uint2 bH[4], bL[4];
            #pragma unroll
            for (int i = 0; i < 4; i++) {
                bH[i] = __ldg(Bh + (nh * 4 + i) * 128 + kt * 4);
                bL[i] = __ldg(Bl + (nh * 4 + i) * 128 + kt * 4);
            }
            #pragma unroll
            for (int i = 0; i < 4; i++) {
                float* cn = c[nh * 4 + i];
                mma_bf16(cn, aH0.x, aH1.x, aH0.y, aH1.y, bH[i].x, bH[i].y);
                mma_bf16(cn, aH0.x, aH1.x, aH0.y, aH1.y, bL[i].x, bL[i].y);
                mma_bf16(cn, aL0.x, aL1.x, aL0.y, aL1.y, bH[i].x, bH[i].y);
            }
        }
    }

    // ---- epilogue: payload stores ----
    float* rbase = out + (long)r * REGION;
    {
        const int head = 2 * p + (fb >> 6);
        const int fh   = (fb & 63) + g_;             // feat-in-head for c0/c1
        float* pbase = rbase + head * 130 + 65;
        #pragma unroll
        for (int nt = 0; nt < 8; nt++) {
            long t0 = tok0 + nt * 8 + 2 * t4;
            float* q0 = pbase + t0 * 1040 + fh;
            q0[0]    = c[nt][0];
            q0[1040] = c[nt][1];
            q0[8]    = c[nt][2];
            q0[1048] = c[nt][3];
        }
    }

    // ---- zeros + scalars: warp wid handles tokens [wid*8, wid*8+8) ----
    {
        const int h0 = 2 * p, h1 = 2 * p + 1, e0 = 4 + 2 * p;
        float tb0 = 0.f, tb1 = 0.f, ebA = 0.f, ebB = 0.f;
        if (r < 2) {
            const float* Bv = r ? Bk : Bq;
            tb0 = __ldg(Bv + h0);        tb1 = __ldg(Bv + h1);
            ebA = __ldg(Bv + 4 + 2 * p); ebB = __ldg(Bv + 5 + 2 * p);
        }
        const float2 z2 = make_float2(0.f, 0.f);
        #pragma unroll
        for (int tt = 0; tt < 8; tt++) {
            long tok = tok0 + wid * 8 + tt;
            float* ob = rbase + tok * 1040;
            float2 s = g_S[tok];                     // {s_mid, s_last}

            ((float2*)(ob + h0 * 130))[lane] = z2;   // head h0 slots 0..63
            ((float2*)(ob + h1 * 130))[lane] = z2;   // head h1 slots 0..63

            if (lane == 0) {
                ob[h0 * 130 + 64]  = 0.f;
                ob[h1 * 130 + 64]  = 0.f;
                ob[h0 * 130 + 129] = (r < 2) ? s.y * tb0 : 0.f;
                ob[h1 * 130 + 129] = (r < 2) ? s.y * tb1 : 0.f;
            }

            if (r < 2) {
                // scalar-only heads e0, e0+1: 130 zeros except slot 65
                ((float2*)(ob + e0 * 130))[lane]       = z2;   // 0..63
                ((float2*)(ob + (e0 + 1) * 130))[lane] = z2;
                float sv = (r == 0) ? s.y : s.x;
                float2 vA = (lane == 0) ? make_float2(0.f, sv * ebA) : z2;
                float2 vB = (lane == 0) ? make_float2(0.f, sv * ebB) : z2;
                ((float2*)(ob + e0 * 130 + 64))[lane]       = vA;  // 64..127
                ((float2*)(ob + (e0 + 1) * 130 + 64))[lane] = vB;
                if (lane == 0) {
                    ((float2*)(ob + e0 * 130 + 128))[0]       = z2;  // 128,129
                    ((float2*)(ob + (e0 + 1) * 130 + 128))[0] = z2;
                }
            }
        }
    }
}

extern "C" void kernel_launch(void* const* d_in, const int* in_sizes, int n_in,
                              void* d_out, int out_size) {
    const float* x  = (const float*)d_in[0];
    const float* Mq = (const float*)d_in[1];
    const float* Bq = (const float*)d_in[2];
    const float* Mk = (const float*)d_in[3];
    const float* Bk = (const float*)d_in[4];
    const float* Mv = (const float*)d_in[5];
    float* out = (float*)d_out;

    const int tokens = in_sizes[0] / 130;   // 32768
    prep_all<<<288, 256>>>(x, Mq, Mk, Mv);
    dim3 grid(8, tokens / 64);
    qkv_mma_kernel<<<grid, 256>>>(Bq, Bk, out);
}

// round 12
// speedup vs baseline: 1.8293x; 1.2370x over previous
#include <cuda_runtime.h>
#include <cuda_bf16.h>
#include <cstdint>

typedef unsigned int u32;

// ============================================================================
// CustomLinear fused q/k/v — mma.sync bf16 hi/lo, FRAGMENT-MAJOR operand store
//   prep (1 kernel): W and X split to bf16 hi/lo and stored in exact
//   mma-fragment order, so every mainloop operand load is one dense LDG.128.
//   main: grid (8 GEMMs fastest, tokens/64). Warp = 16 feats x 64 tokens.
//   A frag uint4 pair: hi = {rowLo.kLo, rowLo.kHi, rowHi.kLo, rowHi.kHi}, lo same
//   B frag uint4:      {bHi0, bHi1, bLo0, bLo1}
// ============================================================================

#define REGION 34078720L           // 8*4096*1040 floats per q/k/v region
#define NTOK   32768
#define NTILE  (NTOK / 8)          // 4096 8-token n-tiles

// A fragments: idx = (((g*8 + mt)*4 + kt)*32 + lane), 2 uint4 each (hi, lo)
__device__ __align__(16) uint4 g_A[8 * 8 * 4 * 32 * 2];      // 256 KB
// B fragments: idx = (tile*4 + kt)*32 + lane
__device__ __align__(16) uint4 g_B1[NTILE * 4 * 32];         // 8 MB (x1)
__device__ __align__(16) uint4 g_B2[NTILE * 4 * 32];         // 8 MB (x2)
__device__ __align__(16) float2 g_S[NTOK];                   // {s_mid, s_last}

__device__ __forceinline__ u32 pack2(float a, float b) {     // low = a, high = b
    __nv_bfloat162 h = __floats2bfloat162_rn(a, b);
    return *(u32*)&h;
}
__device__ __forceinline__ u32 hisplit(float a, float b, float& la, float& lb) {
    __nv_bfloat162 h = __floats2bfloat162_rn(a, b);
    la = a - __bfloat162float(h.x);
    lb = b - __bfloat162float(h.y);
    return *(u32*)&h;
}

__device__ __forceinline__ void mma_bf16(float* c,
                                         u32 a0, u32 a1, u32 a2, u32 a3,
                                         u32 b0, u32 b1) {
    asm volatile(
        "mma.sync.aligned.m16n8k16.row.col.f32.bf16.bf16.f32 "
        "{%0,%1,%2,%3}, {%4,%5,%6,%7}, {%8,%9}, {%0,%1,%2,%3};"
        : "+f"(c[0]), "+f"(c[1]), "+f"(c[2]), "+f"(c[3])
        : "r"(a0), "r"(a1), "r"(a2), "r"(a3), "r"(b0), "r"(b1));
}

// ---------------------------------------------------------------------------
// prep: blocks [0,32) build A fragments; blocks [32,544) build B fragments.
// ---------------------------------------------------------------------------
__global__ void prep_all(const float* __restrict__ x,
                         const float* __restrict__ Mq, const float* __restrict__ Mk,
                         const float* __restrict__ Mv) {
    if (blockIdx.x < 32) {
        // ---- A fragments: one thread per (g, mt, kt, lane) ----
        int t    = blockIdx.x * 256 + threadIdx.x;       // 0..8191
        int lane = t & 31, kt = (t >> 5) & 3, mt = (t >> 7) & 7, g = t >> 10;
        int g_ = lane >> 2, t4 = lane & 3;
        int r = (g < 2) ? 0 : (g < 4) ? 1 : 2;
        int p = (g < 2) ? g : (g < 4) ? g - 2 : g - 4;
        const float* Mbase = (r == 0) ? Mq : (r == 1) ? Mk : Mv;

        int rl = mt * 16 + g_;                           // low row of m16 tile
        int rh = rl + 8;
        const float* rowL = Mbase + (2 * p + (rl >> 6)) * 4096 + (rl & 63) * 64;
        const float* rowH = Mbase + (2 * p + (rh >> 6)) * 4096 + (rh & 63) * 64;
        int klo = kt * 16 + 2 * t4, khi = klo + 8;

        float2 all = *(const float2*)(rowL + klo);
        float2 alh = *(const float2*)(rowL + khi);
        float2 ahl = *(const float2*)(rowH + klo);
        float2 ahh = *(const float2*)(rowH + khi);

        float l0, l1, l2, l3, l4, l5, l6, l7;
        uint4 hi4, lo4;
        hi4.x = hisplit(all.x, all.y, l0, l1);
        hi4.y = hisplit(alh.x, alh.y, l2, l3);
        hi4.z = hisplit(ahl.x, ahl.y, l4, l5);
        hi4.w = hisplit(ahh.x, ahh.y, l6, l7);
        lo4.x = pack2(l0, l1);
        lo4.y = pack2(l2, l3);
        lo4.z = pack2(l4, l5);
        lo4.w = pack2(l6, l7);

        int idx = ((g * 8 + mt) * 4 + kt) * 32 + lane;
        g_A[idx * 2]     = hi4;
        g_A[idx * 2 + 1] = lo4;
    } else {
        // ---- B fragments: one thread per (token, kt) ----
        int t   = (blockIdx.x - 32) * 256 + threadIdx.x;  // 0 .. 131071
        int tok = t >> 2, kt = t & 3;
        const float* xr = x + (long)tok * 130;

        float v1[16], v2[16];
        {
            float2 L;
            #pragma unroll
            for (int j = 0; j < 8; j++) {                 // x1: aligned float2
                L = *(const float2*)(xr + kt * 16 + 2 * j);
                v1[2 * j] = L.x; v1[2 * j + 1] = L.y;
            }
            float2 P[9];
            #pragma unroll
            for (int j = 0; j < 9; j++)                   // x2 via even-offset cover
                P[j] = *(const float2*)(xr + 64 + kt * 16 + 2 * j);
            #pragma unroll
            for (int i = 0; i < 8; i++) {
                v2[2 * i]     = P[i].y;                   // x[65 + kt*16 + 2i]
                v2[2 * i + 1] = P[i + 1].x;               // x[65 + kt*16 + 2i+1]
            }
            if (kt == 3)
                g_S[tok] = make_float2(__ldg(xr + 64), P[8].y);   // {s_mid, x[129]}
        }

        int base = ((tok >> 3) * 4 + kt) * 32 + (tok & 7) * 4;
        #pragma unroll
        for (int t4 = 0; t4 < 4; t4++) {
            int kl = 2 * t4, kh = 8 + 2 * t4;
            float a0, a1, a2, a3;
            uint4 f1, f2;
            f1.x = hisplit(v1[kl], v1[kl + 1], a0, a1);
            f1.y = hisplit(v1[kh], v1[kh + 1], a2, a3);
            f1.z = pack2(a0, a1);
            f1.w = pack2(a2, a3);
            f2.x = hisplit(v2[kl], v2[kl + 1], a0, a1);
            f2.y = hisplit(v2[kh], v2[kh + 1], a2, a3);
            f2.z = pack2(a0, a1);
            f2.w = pack2(a2, a3);
            g_B1[base + t4] = f1;
            g_B2[base + t4] = f2;
        }
    }
}

// ---------------------------------------------------------------------------
// main: warp = 16 feats x 64 tokens; operands via dense LDG.128
// ---------------------------------------------------------------------------
__global__ void __launch_bounds__(256, 3) qkv_mma_kernel(
    const float* __restrict__ Bq, const float* __restrict__ Bk,
    float* __restrict__ out)
{
    const int tid  = threadIdx.x;
    const int wid  = tid >> 5;
    const int lane = tid & 31;
    const int g_   = lane >> 2;
    const int t4   = lane & 3;

    const int g = blockIdx.x;                       // packed GEMM id (fastest)
    const long tok0 = (long)blockIdx.y * 64;
    const int r = (g < 2) ? 0 : (g < 4) ? 1 : 2;    // q / k / v
    const int p = (g < 2) ? g : (g < 4) ? g - 2 : g - 4;
    const int fb = wid * 16;

    const uint4* Ap = g_A + (((g * 8 + wid) * 4) * 32 + lane) * 2;
    const uint4* Bp = ((r == 0) ? g_B2 : g_B1) + (long)blockIdx.y * 1024 + lane;

    float c[8][4];
    #pragma unroll
    for (int nt = 0; nt < 8; nt++)
        { c[nt][0] = 0.f; c[nt][1] = 0.f; c[nt][2] = 0.f; c[nt][3] = 0.f; }

    #pragma unroll
    for (int kt = 0; kt < 4; kt++) {
        uint4 hi = __ldg(Ap + kt * 64);
        uint4 lo = __ldg(Ap + kt * 64 + 1);
        #pragma unroll
        for (int nt = 0; nt < 8; nt++) {
            uint4 b = __ldg(Bp + nt * 128 + kt * 32);
            mma_bf16(c[nt], hi.x, hi.z, hi.y, hi.w, b.x, b.y);   // hiA * hiB
            mma_bf16(c[nt], hi.x, hi.z, hi.y, hi.w, b.z, b.w);   // hiA * loB
            mma_bf16(c[nt], lo.x, lo.z, lo.y, lo.w, b.x, b.y);   // loA * hiB
        }
    }

    // ---- epilogue: payload stores (proven mapping) ----
    float* rbase = out + (long)r * REGION;
    {
        const int head = 2 * p + (fb >> 6);
        const int fh   = (fb & 63) + g_;
        float* pbase = rbase + head * 130 + 65;
        #pragma unroll
        for (int nt = 0; nt < 8; nt++) {
            long t0 = tok0 + nt * 8 + 2 * t4;
            float* q0 = pbase + t0 * 1040 + fh;
            q0[0]    = c[nt][0];
            q0[1040] = c[nt][1];
            q0[8]    = c[nt][2];
            q0[1048] = c[nt][3];
        }
    }

    // ---- zeros + scalars: warp wid handles tokens [wid*8, wid*8+8) ----
    {
        const int h0 = 2 * p, h1 = 2 * p + 1, e0 = 4 + 2 * p;
        float tb0 = 0.f, tb1 = 0.f, ebA = 0.f, ebB = 0.f;
        if (r < 2) {
            const float* Bv = r ? Bk : Bq;
            tb0 = __ldg(Bv + h0);        tb1 = __ldg(Bv + h1);
            ebA = __ldg(Bv + 4 + 2 * p); ebB = __ldg(Bv + 5 + 2 * p);
        }
        const float2 z2 = make_float2(0.f, 0.f);
        #pragma unroll
        for (int tt = 0; tt < 8; tt++) {
            long tok = tok0 + wid * 8 + tt;
            float* ob = rbase + tok * 1040;
            float2 s = g_S[tok];                     // {s_mid, s_last}

            ((float2*)(ob + h0 * 130))[lane] = z2;   // head h0 slots 0..63
            ((float2*)(ob + h1 * 130))[lane] = z2;   // head h1 slots 0..63

            if (lane == 0) {
                ob[h0 * 130 + 64]  = 0.f;
                ob[h1 * 130 + 64]  = 0.f;
                ob[h0 * 130 + 129] = (r < 2) ? s.y * tb0 : 0.f;
                ob[h1 * 130 + 129] = (r < 2) ? s.y * tb1 : 0.f;
            }

            if (r < 2) {
                // scalar-only heads e0, e0+1: 130 zeros except slot 65
                ((float2*)(ob + e0 * 130))[lane]       = z2;   // 0..63
                ((float2*)(ob + (e0 + 1) * 130))[lane] = z2;
                float sv = (r == 0) ? s.y : s.x;
                float2 vA = (lane == 0) ? make_float2(0.f, sv * ebA) : z2;
                float2 vB = (lane == 0) ? make_float2(0.f, sv * ebB) : z2;
                ((float2*)(ob + e0 * 130 + 64))[lane]       = vA;  // 64..127
                ((float2*)(ob + (e0 + 1) * 130 + 64))[lane] = vB;
                if (lane == 0) {
                    ((float2*)(ob + e0 * 130 + 128))[0]       = z2;  // 128,129
                    ((float2*)(ob + (e0 + 1) * 130 + 128))[0] = z2;
                }
            }
        }
    }
}

extern "C" void kernel_launch(void* const* d_in, const int* in_sizes, int n_in,
                              void* d_out, int out_size) {
    const float* x  = (const float*)d_in[0];
    const float* Mq = (const float*)d_in[1];
    const float* Bq = (const float*)d_in[2];
    const float* Mk = (const float*)d_in[3];
    const float* Bk = (const float*)d_in[4];
    const float* Mv = (const float*)d_in[5];
    float* out = (float*)d_out;

    const int tokens = in_sizes[0] / 130;   // 32768
    prep_all<<<544, 256>>>(x, Mq, Mk, Mv);
    dim3 grid(8, tokens / 64);
    qkv_mma_kernel<<<grid, 256>>>(Bq, Bk, out);
}

// round 13
// speedup vs baseline: 1.9532x; 1.0677x over previous
#include <cuda_runtime.h>
#include <cuda_bf16.h>
#include <cstdint>

typedef unsigned int u32;

// ============================================================================
// CustomLinear fused q/k/v — mma.sync bf16 hi/lo, fragment-major operands,
// 512-thread CTAs for latency coverage.
//   prep: W and X split to bf16 hi/lo stored in exact mma-fragment order.
//   main: grid (8 GEMMs fastest, tokens/64); CTA = 128 feats x 64 tokens,
//   16 warps of (16 feats x 32 tokens) -> 16 accumulator regs, occ 2x512.
// ============================================================================

#define REGION 34078720L           // 8*4096*1040 floats per q/k/v region
#define NTOK   32768
#define NTILE  (NTOK / 8)          // 4096 8-token n-tiles

// A fragments: idx = (((g*8 + mt)*4 + kt)*32 + lane), 2 uint4 each (hi, lo)
__device__ __align__(16) uint4 g_A[8 * 8 * 4 * 32 * 2];      // 256 KB
// B fragments: idx = (tile*4 + kt)*32 + lane
__device__ __align__(16) uint4 g_B1[NTILE * 4 * 32];         // 8 MB (x1)
__device__ __align__(16) uint4 g_B2[NTILE * 4 * 32];         // 8 MB (x2)
__device__ __align__(16) float2 g_S[NTOK];                   // {s_mid, s_last}

__device__ __forceinline__ u32 pack2(float a, float b) {     // low = a, high = b
    __nv_bfloat162 h = __floats2bfloat162_rn(a, b);
    return *(u32*)&h;
}
__device__ __forceinline__ u32 hisplit(float a, float b, float& la, float& lb) {
    __nv_bfloat162 h = __floats2bfloat162_rn(a, b);
    la = a - __bfloat162float(h.x);
    lb = b - __bfloat162float(h.y);
    return *(u32*)&h;
}

__device__ __forceinline__ void mma_bf16(float* c,
                                         u32 a0, u32 a1, u32 a2, u32 a3,
                                         u32 b0, u32 b1) {
    asm volatile(
        "mma.sync.aligned.m16n8k16.row.col.f32.bf16.bf16.f32 "
        "{%0,%1,%2,%3}, {%4,%5,%6,%7}, {%8,%9}, {%0,%1,%2,%3};"
        : "+f"(c[0]), "+f"(c[1]), "+f"(c[2]), "+f"(c[3])
        : "r"(a0), "r"(a1), "r"(a2), "r"(a3), "r"(b0), "r"(b1));
}

// ---------------------------------------------------------------------------
// prep: blocks [0,32) build A fragments; blocks [32,544) build B fragments.
// ---------------------------------------------------------------------------
__global__ void prep_all(const float* __restrict__ x,
                         const float* __restrict__ Mq, const float* __restrict__ Mk,
                         const float* __restrict__ Mv) {
    if (blockIdx.x < 32) {
        // ---- A fragments: one thread per (g, mt, kt, lane) ----
        int t    = blockIdx.x * 256 + threadIdx.x;       // 0..8191
        int lane = t & 31, kt = (t >> 5) & 3, mt = (t >> 7) & 7, g = t >> 10;
        int g_ = lane >> 2, t4 = lane & 3;
        int r = (g < 2) ? 0 : (g < 4) ? 1 : 2;
        int p = (g < 2) ? g : (g < 4) ? g - 2 : g - 4;
        const float* Mbase = (r == 0) ? Mq : (r == 1) ? Mk : Mv;

        int rl = mt * 16 + g_;                           // low row of m16 tile
        int rh = rl + 8;
        const float* rowL = Mbase + (2 * p + (rl >> 6)) * 4096 + (rl & 63) * 64;
        const float* rowH = Mbase + (2 * p + (rh >> 6)) * 4096 + (rh & 63) * 64;
        int klo = kt * 16 + 2 * t4, khi = klo + 8;

        float2 all = *(const float2*)(rowL + klo);
        float2 alh = *(const float2*)(rowL + khi);
        float2 ahl = *(const float2*)(rowH + klo);
        float2 ahh = *(const float2*)(rowH + khi);

        float l0, l1, l2, l3, l4, l5, l6, l7;
        uint4 hi4, lo4;
        hi4.x = hisplit(all.x, all.y, l0, l1);
        hi4.y = hisplit(alh.x, alh.y, l2, l3);
        hi4.z = hisplit(ahl.x, ahl.y, l4, l5);
        hi4.w = hisplit(ahh.x, ahh.y, l6, l7);
        lo4.x = pack2(l0, l1);
        lo4.y = pack2(l2, l3);
        lo4.z = pack2(l4, l5);
        lo4.w = pack2(l6, l7);

        int idx = ((g * 8 + mt) * 4 + kt) * 32 + lane;
        g_A[idx * 2]     = hi4;
        g_A[idx * 2 + 1] = lo4;
    } else {
        // ---- B fragments: one thread per (token, kt) ----
        int t   = (blockIdx.x - 32) * 256 + threadIdx.x;  // 0 .. 131071
        int tok = t >> 2, kt = t & 3;
        const float* xr = x + (long)tok * 130;

        float v1[16], v2[16];
        {
            float2 L;
            #pragma unroll
            for (int j = 0; j < 8; j++) {                 // x1: aligned float2
                L = *(const float2*)(xr + kt * 16 + 2 * j);
                v1[2 * j] = L.x; v1[2 * j + 1] = L.y;
            }
            float2 P[9];
            #pragma unroll
            for (int j = 0; j < 9; j++)                   // x2 via even-offset cover
                P[j] = *(const float2*)(xr + 64 + kt * 16 + 2 * j);
            #pragma unroll
            for (int i = 0; i < 8; i++) {
                v2[2 * i]     = P[i].y;                   // x[65 + kt*16 + 2i]
                v2[2 * i + 1] = P[i + 1].x;               // x[65 + kt*16 + 2i+1]
            }
            if (kt == 3)
                g_S[tok] = make_float2(__ldg(xr + 64), P[8].y);   // {s_mid, x[129]}
        }

        int base = ((tok >> 3) * 4 + kt) * 32 + (tok & 7) * 4;
        #pragma unroll
        for (int t4 = 0; t4 < 4; t4++) {
            int kl = 2 * t4, kh = 8 + 2 * t4;
            float a0, a1, a2, a3;
            uint4 f1, f2;
            f1.x = hisplit(v1[kl], v1[kl + 1], a0, a1);
            f1.y = hisplit(v1[kh], v1[kh + 1], a2, a3);
            f1.z = pack2(a0, a1);
            f1.w = pack2(a2, a3);
            f2.x = hisplit(v2[kl], v2[kl + 1], a0, a1);
            f2.y = hisplit(v2[kh], v2[kh + 1], a2, a3);
            f2.z = pack2(a0, a1);
            f2.w = pack2(a2, a3);
            g_B1[base + t4] = f1;
            g_B2[base + t4] = f2;
        }
    }
}

// ---------------------------------------------------------------------------
// main: 512 threads; warp = 16 feats x 32 tokens; dense LDG.128 operands
// ---------------------------------------------------------------------------
__global__ void __launch_bounds__(512, 2) qkv_mma_kernel(
    const float* __restrict__ Bq, const float* __restrict__ Bk,
    float* __restrict__ out)
{
    const int tid  = threadIdx.x;
    const int wid  = tid >> 5;           // 0..15
    const int lane = tid & 31;
    const int g_   = lane >> 2;
    const int t4   = lane & 3;

    const int g = blockIdx.x;                       // packed GEMM id (fastest)
    const long tok0 = (long)blockIdx.y * 64;
    const int r = (g < 2) ? 0 : (g < 4) ? 1 : 2;    // q / k / v
    const int p = (g < 2) ? g : (g < 4) ? g - 2 : g - 4;

    const int fi = wid & 7;              // feat tile (16 feats)
    const int th = wid >> 3;             // token half (32 tokens)
    const int fb = fi * 16;

    const uint4* Ap = g_A + (((g * 8 + fi) * 4) * 32 + lane) * 2;
    const uint4* Bp = ((r == 0) ? g_B2 : g_B1)
                      + (long)blockIdx.y * 1024 + th * 512 + lane;

    float c[4][4];
    #pragma unroll
    for (int nt = 0; nt < 4; nt++)
        { c[nt][0] = 0.f; c[nt][1] = 0.f; c[nt][2] = 0.f; c[nt][3] = 0.f; }

    #pragma unroll
    for (int kt = 0; kt < 4; kt++) {
        uint4 hi = __ldg(Ap + kt * 64);
        uint4 lo = __ldg(Ap + kt * 64 + 1);
        #pragma unroll
        for (int nt = 0; nt < 4; nt++) {
            uint4 b = __ldg(Bp + nt * 128 + kt * 32);
            mma_bf16(c[nt], hi.x, hi.z, hi.y, hi.w, b.x, b.y);   // hiA * hiB
            mma_bf16(c[nt], hi.x, hi.z, hi.y, hi.w, b.z, b.w);   // hiA * loB
            mma_bf16(c[nt], lo.x, lo.z, lo.y, lo.w, b.x, b.y);   // loA * hiB
        }
    }

    // ---- epilogue: payload stores (proven mapping) ----
    float* rbase = out + (long)r * REGION;
    {
        const int head = 2 * p + (fb >> 6);
        const int fh   = (fb & 63) + g_;
        float* pbase = rbase + head * 130 + 65;
        #pragma unroll
        for (int nt = 0; nt < 4; nt++) {
            long t0 = tok0 + th * 32 + nt * 8 + 2 * t4;
            float* q0 = pbase + t0 * 1040 + fh;
            q0[0]    = c[nt][0];
            q0[1040] = c[nt][1];
            q0[8]    = c[nt][2];
            q0[1048] = c[nt][3];
        }
    }

    // ---- zeros + scalars: warp wid handles tokens [wid*4, wid*4+4) ----
    {
        const int h0 = 2 * p, h1 = 2 * p + 1, e0 = 4 + 2 * p;
        float tb0 = 0.f, tb1 = 0.f, ebA = 0.f, ebB = 0.f;
        if (r < 2) {
            const float* Bv = r ? Bk : Bq;
            tb0 = __ldg(Bv + h0);        tb1 = __ldg(Bv + h1);
            ebA = __ldg(Bv + 4 + 2 * p); ebB = __ldg(Bv + 5 + 2 * p);
        }
        const float2 z2 = make_float2(0.f, 0.f);
        #pragma unroll
        for (int tt = 0; tt < 4; tt++) {
            long tok = tok0 + wid * 4 + tt;
            float* ob = rbase + tok * 1040;
            float2 s = g_S[tok];                     // {s_mid, s_last}

            ((float2*)(ob + h0 * 130))[lane] = z2;   // head h0 slots 0..63
            ((float2*)(ob + h1 * 130))[lane] = z2;   // head h1 slots 0..63

            if (lane == 0) {
                ob[h0 * 130 + 64]  = 0.f;
                ob[h1 * 130 + 64]  = 0.f;
                ob[h0 * 130 + 129] = (r < 2) ? s.y * tb0 : 0.f;
                ob[h1 * 130 + 129] = (r < 2) ? s.y * tb1 : 0.f;
            }

            if (r < 2) {
                // scalar-only heads e0, e0+1: 130 zeros except slot 65
                ((float2*)(ob + e0 * 130))[lane]       = z2;   // 0..63
                ((float2*)(ob + (e0 + 1) * 130))[lane] = z2;
                float sv = (r == 0) ? s.y : s.x;
                float2 vA = (lane == 0) ? make_float2(0.f, sv * ebA) : z2;
                float2 vB = (lane == 0) ? make_float2(0.f, sv * ebB) : z2;
                ((float2*)(ob + e0 * 130 + 64))[lane]       = vA;  // 64..127
                ((float2*)(ob + (e0 + 1) * 130 + 64))[lane] = vB;
                if (lane == 0) {
                    ((float2*)(ob + e0 * 130 + 128))[0]       = z2;  // 128,129
                    ((float2*)(ob + (e0 + 1) * 130 + 128))[0] = z2;
                }
            }
        }
    }
}

extern "C" void kernel_launch(void* const* d_in, const int* in_sizes, int n_in,
                              void* d_out, int out_size) {
    const float* x  = (const float*)d_in[0];
    const float* Mq = (const float*)d_in[1];
    const float* Bq = (const float*)d_in[2];
    const float* Mk = (const float*)d_in[3];
    const float* Bk = (const float*)d_in[4];
    const float* Mv = (const float*)d_in[5];
    float* out = (float*)d_out;

    const int tokens = in_sizes[0] / 130;   // 32768
    prep_all<<<544, 256>>>(x, Mq, Mk, Mv);
    dim3 grid(8, tokens / 64);
    qkv_mma_kernel<<<grid, 512>>>(Bq, Bk, out);
}